// round 12
// baseline (speedup 1.0000x reference)
#include <cuda_runtime.h>
#include <cuda_fp16.h>
#include <math.h>

#define N_NODES 100000
#define N_EDGES 1600000
#define NH 4
#define DIN 128
#define DOUT 32
#define NB_SCAN 98   // 98*1024 = 100352 >= N_NODES

#define CTOT 128              // NH*DOUT combined output cols
#define WPITCH 132            // smem pitch for W (conflict-free LDS.128)
#define NPB 128               // gemm nodes per block (512 threads)
#define GEMM_SMEM ((CTOT*WPITCH + NPB*DIN) * 4)   // 67584 + 65536 = 133120 B

// ---------------- scratch (static __device__, no allocation) ----------------
__device__ __align__(16) __half d_Hwh[N_NODES * CTOT];  // [n][c] fp16, 25.6MB
__device__ float4 d_ssrc4[N_NODES];       // [n] -> (s_src for h=0..3)
__device__ float4 d_stgt4[N_NODES];
__device__ int    d_hist[N_NODES];
__device__ int    d_off[N_NODES + 1];
__device__ int    d_cursor[N_NODES];
__device__ int    d_blocksums[128];
__device__ int    d_sorted_src[N_EDGES];
__device__ int    d_is64;

__device__ __forceinline__ void fma2(unsigned long long& acc,
                                     unsigned long long a,
                                     unsigned long long b) {
    asm("fma.rn.f32x2 %0, %1, %2, %0;" : "+l"(acc) : "l"(a), "l"(b));
}
__device__ __forceinline__ float pairsum(unsigned long long a) {
    float lo = __uint_as_float((unsigned)(a & 0xffffffffull));
    float hi = __uint_as_float((unsigned)(a >> 32));
    return lo + hi;
}

// ---------------- init: zero hist + detect edge dtype ----------------
// int64 with values < 2^31 => every odd 32-bit word is zero.
__global__ void k_init(const unsigned int* __restrict__ w) {
    int i = blockIdx.x * 256 + threadIdx.x;
    if (i < N_NODES) d_hist[i] = 0;
    if (blockIdx.x == 0) {
        int nz = 0;
        for (int j = 0; j < 8; j++)
            nz |= (w[2 * (threadIdx.x * 8 + j) + 1] != 0u) ? 1 : 0;
        int any = __syncthreads_or(nz);
        if (threadIdx.x == 0) d_is64 = any ? 0 : 1;
    }
}

// histogram of targets: 4 edges per thread, int4 loads
__global__ void k_hist(const int* __restrict__ p) {
    int e0 = (blockIdx.x * blockDim.x + threadIdx.x) * 4;
    if (e0 >= N_EDGES) return;
    if (d_is64) {
        const int4* q = (const int4*)(p + 2 * N_EDGES);   // targets as int64
        int4 a = q[e0 >> 1];
        int4 b = q[(e0 >> 1) + 1];
        atomicAdd(&d_hist[a.x], 1);
        atomicAdd(&d_hist[a.z], 1);
        atomicAdd(&d_hist[b.x], 1);
        atomicAdd(&d_hist[b.z], 1);
    } else {
        const int4* q = (const int4*)(p + N_EDGES);
        int4 a = q[e0 >> 2];
        atomicAdd(&d_hist[a.x], 1);
        atomicAdd(&d_hist[a.y], 1);
        atomicAdd(&d_hist[a.z], 1);
        atomicAdd(&d_hist[a.w], 1);
    }
}

// ---------------- block sums of hist ----------------
__global__ void k_scan1() {
    __shared__ int ws[8];
    int b = blockIdx.x, tid = threadIdx.x;
    int lane = tid & 31, wid = tid >> 5;
    int sum = 0;
    for (int j = 0; j < 4; j++) {
        int idx = b * 1024 + tid + j * 256;
        if (idx < N_NODES) sum += d_hist[idx];
    }
#pragma unroll
    for (int off = 16; off > 0; off >>= 1)
        sum += __shfl_xor_sync(0xffffffffu, sum, off);
    if (lane == 0) ws[wid] = sum;
    __syncthreads();
    if (tid == 0) {
        int s = 0;
        for (int j = 0; j < 8; j++) s += ws[j];
        d_blocksums[b] = s;
    }
}

// scan of hist: shfl-based, with inlined redundant scan of the 98 block sums
__global__ void k_scan3() {
    __shared__ int bs[128];
    __shared__ int warpsums[32];
    int b = blockIdx.x, tid = threadIdx.x;
    int lane = tid & 31, wid = tid >> 5;

    if (tid < 128) bs[tid] = (tid < NB_SCAN) ? d_blocksums[tid] : 0;
    __syncthreads();
    if (wid == 0) {
        int a0 = bs[4 * lane], a1 = bs[4 * lane + 1];
        int a2 = bs[4 * lane + 2], a3 = bs[4 * lane + 3];
        int s = a0 + a1 + a2 + a3;
        int inc = s;
#pragma unroll
        for (int off = 1; off < 32; off <<= 1) {
            int n = __shfl_up_sync(0xffffffffu, inc, off);
            if (lane >= off) inc += n;
        }
        int excl = inc - s;
        bs[4 * lane]     = excl;
        bs[4 * lane + 1] = excl + a0;
        bs[4 * lane + 2] = excl + a0 + a1;
        bs[4 * lane + 3] = excl + a0 + a1 + a2;
    }
    __syncthreads();
    int blockbase = bs[b];

    int idx = b * 1024 + tid;
    int v = (idx < N_NODES) ? d_hist[idx] : 0;
    int inc = v;
#pragma unroll
    for (int off = 1; off < 32; off <<= 1) {
        int n = __shfl_up_sync(0xffffffffu, inc, off);
        if (lane >= off) inc += n;
    }
    if (lane == 31) warpsums[wid] = inc;
    __syncthreads();
    if (wid == 0) {
        int wv = warpsums[lane];
        int winc = wv;
#pragma unroll
        for (int off = 1; off < 32; off <<= 1) {
            int n = __shfl_up_sync(0xffffffffu, winc, off);
            if (lane >= off) winc += n;
        }
        warpsums[lane] = winc - wv;
    }
    __syncthreads();
    if (idx < N_NODES) {
        int excl = inc - v + warpsums[wid] + blockbase;
        d_off[idx] = excl;
        d_cursor[idx] = excl;
    }
    if (b == 0 && tid == 0) d_off[N_NODES] = N_EDGES;
}

// scatter src ids into CSR order: 4 edges per thread, int4 loads
__global__ void k_scatter(const int* __restrict__ p) {
    int e0 = (blockIdx.x * blockDim.x + threadIdx.x) * 4;
    if (e0 >= N_EDGES) return;
    int s[4], t[4];
    if (d_is64) {
        const int4* qs = (const int4*)p;
        const int4* qt = (const int4*)(p + 2 * N_EDGES);
        int4 sa = qs[e0 >> 1], sb = qs[(e0 >> 1) + 1];
        int4 ta = qt[e0 >> 1], tb = qt[(e0 >> 1) + 1];
        s[0] = sa.x; s[1] = sa.z; s[2] = sb.x; s[3] = sb.z;
        t[0] = ta.x; t[1] = ta.z; t[2] = tb.x; t[3] = tb.z;
    } else {
        int4 sa = ((const int4*)p)[e0 >> 2];
        int4 ta = ((const int4*)(p + N_EDGES))[e0 >> 2];
        s[0] = sa.x; s[1] = sa.y; s[2] = sa.z; s[3] = sa.w;
        t[0] = ta.x; t[1] = ta.y; t[2] = ta.z; t[3] = ta.w;
    }
#pragma unroll
    for (int j = 0; j < 4; j++) {
        int pos = atomicAdd(&d_cursor[t[j]], 1);
        d_sorted_src[pos] = s[j];
    }
}

// ---------------- Hw[n][c] = sum_k Hin[n][k] * W[c][k]  (c = h*32+o) ----------
// 512 threads, tile 128 nodes x 128 cols, per-warp 8 nodes x 128 cols,
// f32x2 packed FFMA. Epilogue: fp16 Hw store + fused fp32 score reduction.
__global__ void __launch_bounds__(512, 1) k_gemm(const float* __restrict__ Hin,
                                                 const float* __restrict__ W,
                                                 const float* __restrict__ Asrc,
                                                 const float* __restrict__ Atgt) {
    extern __shared__ float smem[];
    float* Wsh = smem;                  // [128][WPITCH]
    float* Hsh = smem + CTOT * WPITCH;  // [128][128]

    int tid = threadIdx.x;
    int tx = tid & 31;   // col lane: cols tx + 32*j  (head j, out chan tx)
    int wp = tid >> 5;   // warp: nodes wp*8 + i

    const float4* W4 = (const float4*)W;
    for (int it = 0; it < 8; it++) {
        int idx = tid + it * 512;
        int c = idx >> 5, k4 = idx & 31;
        *(float4*)(Wsh + c * WPITCH + k4 * 4) = W4[idx];
    }

    int n0 = blockIdx.x * NPB;
    const float4* H4 = (const float4*)Hin;
    for (int it = 0; it < 8; it++) {
        int idx = tid + it * 512;
        int row = idx >> 5, c4 = idx & 31;
        int n = n0 + row;
        float4 v = make_float4(0.f, 0.f, 0.f, 0.f);
        if (n < N_NODES) v = H4[n * 32 + c4];
        *(float4*)(Hsh + row * DIN + c4 * 4) = v;
    }
    __syncthreads();

    unsigned long long acc[8][4];
#pragma unroll
    for (int i = 0; i < 8; i++)
#pragma unroll
        for (int j = 0; j < 4; j++) acc[i][j] = 0ull;

    const float* hbase = Hsh + (wp * 8) * DIN;
    const float* wbase = Wsh + tx * WPITCH;

#pragma unroll 2
    for (int k4 = 0; k4 < 32; k4++) {
        ulonglong2 wv[4];
#pragma unroll
        for (int j = 0; j < 4; j++)
            wv[j] = *(const ulonglong2*)(wbase + j * 32 * WPITCH + k4 * 4);
#pragma unroll
        for (int i = 0; i < 8; i++) {
            ulonglong2 hv = *(const ulonglong2*)(hbase + i * DIN + k4 * 4);
#pragma unroll
            for (int j = 0; j < 4; j++) {
                fma2(acc[i][j], hv.x, wv[j].x);
                fma2(acc[i][j], hv.y, wv[j].y);
            }
        }
    }

    float a_s[4], a_t[4];
#pragma unroll
    for (int j = 0; j < 4; j++) {
        a_s[j] = Asrc[j * 32 + tx];
        a_t[j] = Atgt[j * 32 + tx];
    }

#pragma unroll
    for (int i = 0; i < 8; i++) {
        int n = n0 + wp * 8 + i;
        if (n >= N_NODES) break;     // uniform across the warp
        float av[4], vs[4], vt[4];
#pragma unroll
        for (int j = 0; j < 4; j++) {
            av[j] = pairsum(acc[i][j]);
            vs[j] = av[j] * a_s[j];
            vt[j] = av[j] * a_t[j];
        }
#pragma unroll
        for (int j = 0; j < 4; j++)
            d_Hwh[n * CTOT + tx + 32 * j] = __float2half_rn(av[j]);
#pragma unroll
        for (int off = 16; off > 0; off >>= 1) {
#pragma unroll
            for (int j = 0; j < 4; j++) {
                vs[j] += __shfl_xor_sync(0xffffffffu, vs[j], off);
                vt[j] += __shfl_xor_sync(0xffffffffu, vt[j], off);
            }
        }
        if (tx == 0) {
            d_ssrc4[n] = make_float4(vs[0], vs[1], vs[2], vs[3]);
            d_stgt4[n] = make_float4(vt[0], vt[1], vt[2], vt[3]);
        }
    }
}

// ---------------- per-target softmax + aggregation + elu (all 4 heads) -------
// One warp per target node, single pass over edges with unnormalized
// exp-weighted sums; full 32-edge chunks run a 4-way-unrolled gather
// (4 independent LDG.64 in flight) for memory-level parallelism.
__global__ void k_agg(float* __restrict__ out) {
    __shared__ int    sns[8][32];
    __shared__ float4 al[8][32];
    int w = threadIdx.x >> 5;
    int lane = threadIdx.x & 31;
    int t = blockIdx.x * 8 + w;
    if (t >= N_NODES) return;

    int start = d_off[t];
    int end = d_off[t + 1];
    float4 st = d_stgt4[t];

    int hsel = lane >> 3;
    const __half* hwbase = d_Hwh + (long)lane * 4;
    float4 acc = make_float4(0.f, 0.f, 0.f, 0.f);
    float s0 = 0.f, s1 = 0.f, s2 = 0.f, s3 = 0.f;

    for (int base = start; base < end; base += 32) {
        int i = base + lane;
        float ax = 0.f, ay = 0.f, az = 0.f, aw = 0.f;
        int sn = 0;
        if (i < end) {
            sn = d_sorted_src[i];
            float4 e4 = d_ssrc4[sn];
            float e0 = e4.x + st.x; e0 = fmaxf(e0, 0.2f * e0);
            float e1 = e4.y + st.y; e1 = fmaxf(e1, 0.2f * e1);
            float e2 = e4.z + st.z; e2 = fmaxf(e2, 0.2f * e2);
            float e3 = e4.w + st.w; e3 = fmaxf(e3, 0.2f * e3);
            ax = __expf(e0);
            ay = __expf(e1);
            az = __expf(e2);
            aw = __expf(e3);
            s0 += ax; s1 += ay; s2 += az; s3 += aw;
        }
        sns[w][lane] = sn;
        al[w][lane] = make_float4(ax, ay, az, aw);
        __syncwarp();
        int cnt = end - base;
        if (cnt >= 32) {
#pragma unroll
            for (int j0 = 0; j0 < 32; j0 += 4) {
                int sj0 = sns[w][j0 + 0];
                int sj1 = sns[w][j0 + 1];
                int sj2 = sns[w][j0 + 2];
                int sj3 = sns[w][j0 + 3];
                uint2 h0 = *(const uint2*)(hwbase + (long)sj0 * CTOT);
                uint2 h1 = *(const uint2*)(hwbase + (long)sj1 * CTOT);
                uint2 h2 = *(const uint2*)(hwbase + (long)sj2 * CTOT);
                uint2 h3 = *(const uint2*)(hwbase + (long)sj3 * CTOT);
                float a0 = ((const float*)&al[w][j0 + 0])[hsel];
                float a1 = ((const float*)&al[w][j0 + 1])[hsel];
                float a2 = ((const float*)&al[w][j0 + 2])[hsel];
                float a3 = ((const float*)&al[w][j0 + 3])[hsel];
                float2 f;
                f = __half22float2(*(const __half2*)&h0.x);
                acc.x += a0 * f.x; acc.y += a0 * f.y;
                f = __half22float2(*(const __half2*)&h0.y);
                acc.z += a0 * f.x; acc.w += a0 * f.y;
                f = __half22float2(*(const __half2*)&h1.x);
                acc.x += a1 * f.x; acc.y += a1 * f.y;
                f = __half22float2(*(const __half2*)&h1.y);
                acc.z += a1 * f.x; acc.w += a1 * f.y;
                f = __half22float2(*(const __half2*)&h2.x);
                acc.x += a2 * f.x; acc.y += a2 * f.y;
                f = __half22float2(*(const __half2*)&h2.y);
                acc.z += a2 * f.x; acc.w += a2 * f.y;
                f = __half22float2(*(const __half2*)&h3.x);
                acc.x += a3 * f.x; acc.y += a3 * f.y;
                f = __half22float2(*(const __half2*)&h3.y);
                acc.z += a3 * f.x; acc.w += a3 * f.y;
            }
        } else {
            for (int j = 0; j < cnt; j++) {
                int sj = sns[w][j];
                float a = ((const float*)&al[w][j])[hsel];
                uint2 hv = *(const uint2*)(hwbase + (long)sj * CTOT);
                float2 f01 = __half22float2(*(const __half2*)&hv.x);
                float2 f23 = __half22float2(*(const __half2*)&hv.y);
                acc.x += a * f01.x;
                acc.y += a * f01.y;
                acc.z += a * f23.x;
                acc.w += a * f23.y;
            }
        }
        __syncwarp();
    }

#pragma unroll
    for (int off = 16; off > 0; off >>= 1) {
        s0 += __shfl_xor_sync(0xffffffffu, s0, off);
        s1 += __shfl_xor_sync(0xffffffffu, s1, off);
        s2 += __shfl_xor_sync(0xffffffffu, s2, off);
        s3 += __shfl_xor_sync(0xffffffffu, s3, off);
    }
    float sh = (hsel == 0) ? s0 : (hsel == 1) ? s1 : (hsel == 2) ? s2 : s3;
    float inv = (sh > 0.f) ? 1.f / sh : 0.f;
    acc.x *= inv; acc.y *= inv; acc.z *= inv; acc.w *= inv;

    float4 r;
    r.x = acc.x > 0.f ? acc.x : expm1f(acc.x);
    r.y = acc.y > 0.f ? acc.y : expm1f(acc.y);
    r.z = acc.z > 0.f ? acc.z : expm1f(acc.z);
    r.w = acc.w > 0.f ? acc.w : expm1f(acc.w);
    int o = (lane & 7) * 4;
    *(float4*)(out + ((long)hsel * N_NODES + t) * DOUT + o) = r;
}

// ---------------- launcher ----------------
extern "C" void kernel_launch(void* const* d_in, const int* in_sizes, int n_in,
                              void* d_out, int out_size) {
    const float* Hin  = (const float*)d_in[0];
    const int*   ei   = (const int*)d_in[1];
    const float* W    = (const float*)d_in[2];
    const float* Asrc = (const float*)d_in[3];
    const float* Atgt = (const float*)d_in[4];
    float* out = (float*)d_out;

    cudaFuncSetAttribute(k_gemm, cudaFuncAttributeMaxDynamicSharedMemorySize,
                         GEMM_SMEM);

    k_init<<<(N_NODES + 255) / 256, 256>>>((const unsigned int*)ei);
    k_hist<<<(N_EDGES / 4 + 255) / 256, 256>>>(ei);
    k_scan1<<<NB_SCAN, 256>>>();
    k_scan3<<<NB_SCAN, 1024>>>();
    k_scatter<<<(N_EDGES / 4 + 255) / 256, 256>>>(ei);
    k_gemm<<<(N_NODES + NPB - 1) / NPB, 256 * 2, GEMM_SMEM>>>(Hin, W, Asrc, Atgt);
    k_agg<<<(N_NODES + 7) / 8, 256>>>(out);
}

// round 13
// speedup vs baseline: 1.2100x; 1.2100x over previous
#include <cuda_runtime.h>
#include <cuda_fp16.h>
#include <math.h>

#define N_NODES 100000
#define N_EDGES 1600000
#define NH 4
#define DIN 128
#define DOUT 32
#define NB_SCAN 98   // 98*1024 = 100352 >= N_NODES

#define CTOT 128              // NH*DOUT combined output cols
#define WPITCH 132            // smem pitch for W (conflict-free LDS.128)
#define NPB 64                // gemm nodes per block (256 threads, 2 CTA/SM)
#define GEMM_SMEM ((CTOT*WPITCH + NPB*DIN) * 4)   // 67584 + 32768 = 100352 B

// ---------------- scratch (static __device__, no allocation) ----------------
__device__ __align__(16) __half d_Hwh[N_NODES * CTOT];  // [n][c] fp16, 25.6MB
__device__ float4 d_ssrc4[N_NODES];       // [n] -> (s_src for h=0..3)
__device__ float4 d_stgt4[N_NODES];
__device__ int    d_hist[N_NODES];
__device__ int    d_off[N_NODES + 1];
__device__ int    d_cursor[N_NODES];
__device__ int    d_blocksums[128];
__device__ int    d_sorted_src[N_EDGES];
__device__ int    d_is64;

__device__ __forceinline__ void fma2(unsigned long long& acc,
                                     unsigned long long a,
                                     unsigned long long b) {
    asm("fma.rn.f32x2 %0, %1, %2, %0;" : "+l"(acc) : "l"(a), "l"(b));
}
__device__ __forceinline__ float pairsum(unsigned long long a) {
    float lo = __uint_as_float((unsigned)(a & 0xffffffffull));
    float hi = __uint_as_float((unsigned)(a >> 32));
    return lo + hi;
}

// ---------------- init: zero hist + detect edge dtype ----------------
// int64 with values < 2^31 => every odd 32-bit word is zero.
__global__ void k_init(const unsigned int* __restrict__ w) {
    int i = blockIdx.x * 256 + threadIdx.x;
    if (i < N_NODES) d_hist[i] = 0;
    if (blockIdx.x == 0) {
        int nz = 0;
        for (int j = 0; j < 8; j++)
            nz |= (w[2 * (threadIdx.x * 8 + j) + 1] != 0u) ? 1 : 0;
        int any = __syncthreads_or(nz);
        if (threadIdx.x == 0) d_is64 = any ? 0 : 1;
    }
}

// histogram of targets, reading edge_index directly
__global__ void k_hist(const int* __restrict__ p) {
    int e = blockIdx.x * blockDim.x + threadIdx.x;
    if (e >= N_EDGES) return;
    int t = d_is64 ? p[2 * (N_EDGES + e)] : p[N_EDGES + e];
    atomicAdd(&d_hist[t], 1);
}

// ---------------- block sums of hist (shfl) ----------------
__global__ void k_scan1() {
    __shared__ int ws[8];
    int b = blockIdx.x, tid = threadIdx.x;
    int lane = tid & 31, wid = tid >> 5;
    int sum = 0;
    for (int j = 0; j < 4; j++) {
        int idx = b * 1024 + tid + j * 256;
        if (idx < N_NODES) sum += d_hist[idx];
    }
#pragma unroll
    for (int off = 16; off > 0; off >>= 1)
        sum += __shfl_xor_sync(0xffffffffu, sum, off);
    if (lane == 0) ws[wid] = sum;
    __syncthreads();
    if (tid == 0) {
        int s = 0;
        for (int j = 0; j < 8; j++) s += ws[j];
        d_blocksums[b] = s;
    }
}

// scan of hist: shfl-based, with inlined redundant scan of the 98 block sums
__global__ void k_scan3() {
    __shared__ int bs[128];
    __shared__ int warpsums[32];
    int b = blockIdx.x, tid = threadIdx.x;
    int lane = tid & 31, wid = tid >> 5;

    if (tid < 128) bs[tid] = (tid < NB_SCAN) ? d_blocksums[tid] : 0;
    __syncthreads();
    if (wid == 0) {
        int a0 = bs[4 * lane], a1 = bs[4 * lane + 1];
        int a2 = bs[4 * lane + 2], a3 = bs[4 * lane + 3];
        int s = a0 + a1 + a2 + a3;
        int inc = s;
#pragma unroll
        for (int off = 1; off < 32; off <<= 1) {
            int n = __shfl_up_sync(0xffffffffu, inc, off);
            if (lane >= off) inc += n;
        }
        int excl = inc - s;
        bs[4 * lane]     = excl;
        bs[4 * lane + 1] = excl + a0;
        bs[4 * lane + 2] = excl + a0 + a1;
        bs[4 * lane + 3] = excl + a0 + a1 + a2;
    }
    __syncthreads();
    int blockbase = bs[b];

    int idx = b * 1024 + tid;
    int v = (idx < N_NODES) ? d_hist[idx] : 0;
    int inc = v;
#pragma unroll
    for (int off = 1; off < 32; off <<= 1) {
        int n = __shfl_up_sync(0xffffffffu, inc, off);
        if (lane >= off) inc += n;
    }
    if (lane == 31) warpsums[wid] = inc;
    __syncthreads();
    if (wid == 0) {
        int wv = warpsums[lane];
        int winc = wv;
#pragma unroll
        for (int off = 1; off < 32; off <<= 1) {
            int n = __shfl_up_sync(0xffffffffu, winc, off);
            if (lane >= off) winc += n;
        }
        warpsums[lane] = winc - wv;
    }
    __syncthreads();
    if (idx < N_NODES) {
        int excl = inc - v + warpsums[wid] + blockbase;
        d_off[idx] = excl;
        d_cursor[idx] = excl;
    }
    if (b == 0 && tid == 0) d_off[N_NODES] = N_EDGES;
}

// scatter src ids into CSR order, reading edge_index directly
__global__ void k_scatter(const int* __restrict__ p) {
    int e = blockIdx.x * blockDim.x + threadIdx.x;
    if (e >= N_EDGES) return;
    int s, t;
    if (d_is64) {
        s = p[2 * e];
        t = p[2 * (N_EDGES + e)];
    } else {
        s = p[e];
        t = p[N_EDGES + e];
    }
    int pos = atomicAdd(&d_cursor[t], 1);
    d_sorted_src[pos] = s;
}

// ---------------- Hw[n][c] = sum_k Hin[n][k] * W[c][k]  (c = h*32+o) ----------
// 256 threads, tile 64 nodes x 128 cols, reg tile 8 nodes x 4 cols per thread,
// f32x2 packed FFMA, 2 CTAs/SM. Epilogue: fp16 Hw store + fused fp32 score
// reduction (warp owns all 128 cols of its 8 nodes; col group j == head j).
__global__ void __launch_bounds__(256, 2) k_gemm(const float* __restrict__ Hin,
                                                 const float* __restrict__ W,
                                                 const float* __restrict__ Asrc,
                                                 const float* __restrict__ Atgt) {
    extern __shared__ float smem[];
    float* Wsh = smem;                  // [128][WPITCH]
    float* Hsh = smem + CTOT * WPITCH;  // [64][128]

    int tid = threadIdx.x;
    int tx = tid & 31;   // col lane: cols tx + 32*j  (head j, out chan tx)
    int wp = tid >> 5;   // warp: nodes wp*8 + i

    const float4* W4 = (const float4*)W;
    for (int it = 0; it < 16; it++) {
        int idx = tid + it * 256;
        int c = idx >> 5, k4 = idx & 31;
        *(float4*)(Wsh + c * WPITCH + k4 * 4) = W4[idx];
    }

    int n0 = blockIdx.x * NPB;
    const float4* H4 = (const float4*)Hin;
    for (int it = 0; it < 8; it++) {
        int idx = tid + it * 256;
        int row = idx >> 5, c4 = idx & 31;
        int n = n0 + row;
        float4 v = make_float4(0.f, 0.f, 0.f, 0.f);
        if (n < N_NODES) v = H4[n * 32 + c4];
        *(float4*)(Hsh + row * DIN + c4 * 4) = v;
    }
    __syncthreads();

    unsigned long long acc[8][4];
#pragma unroll
    for (int i = 0; i < 8; i++)
#pragma unroll
        for (int j = 0; j < 4; j++) acc[i][j] = 0ull;

    const float* hbase = Hsh + (wp * 8) * DIN;
    const float* wbase = Wsh + tx * WPITCH;

#pragma unroll 2
    for (int k4 = 0; k4 < 32; k4++) {
        ulonglong2 wv[4];
#pragma unroll
        for (int j = 0; j < 4; j++)
            wv[j] = *(const ulonglong2*)(wbase + j * 32 * WPITCH + k4 * 4);
#pragma unroll
        for (int i = 0; i < 8; i++) {
            ulonglong2 hv = *(const ulonglong2*)(hbase + i * DIN + k4 * 4);
#pragma unroll
            for (int j = 0; j < 4; j++) {
                fma2(acc[i][j], hv.x, wv[j].x);
                fma2(acc[i][j], hv.y, wv[j].y);
            }
        }
    }

    float a_s[4], a_t[4];
#pragma unroll
    for (int j = 0; j < 4; j++) {
        a_s[j] = Asrc[j * 32 + tx];
        a_t[j] = Atgt[j * 32 + tx];
    }

#pragma unroll
    for (int i = 0; i < 8; i++) {
        int n = n0 + wp * 8 + i;
        if (n >= N_NODES) break;     // uniform across the warp
        float av[4], vs[4], vt[4];
#pragma unroll
        for (int j = 0; j < 4; j++) {
            av[j] = pairsum(acc[i][j]);
            vs[j] = av[j] * a_s[j];
            vt[j] = av[j] * a_t[j];
        }
#pragma unroll
        for (int j = 0; j < 4; j++)
            d_Hwh[n * CTOT + tx + 32 * j] = __float2half_rn(av[j]);
#pragma unroll
        for (int off = 16; off > 0; off >>= 1) {
#pragma unroll
            for (int j = 0; j < 4; j++) {
                vs[j] += __shfl_xor_sync(0xffffffffu, vs[j], off);
                vt[j] += __shfl_xor_sync(0xffffffffu, vt[j], off);
            }
        }
        if (tx == 0) {
            d_ssrc4[n] = make_float4(vs[0], vs[1], vs[2], vs[3]);
            d_stgt4[n] = make_float4(vt[0], vt[1], vt[2], vt[3]);
        }
    }
}

// ---------------- per-target softmax + aggregation + elu (all 4 heads) -------
// One warp per target node, single pass: unnormalized exp-weighted sums plus
// per-head denominators, normalize at the end (no max-subtraction needed).
__global__ void k_agg(float* __restrict__ out) {
    __shared__ int    sns[8][32];
    __shared__ float4 al[8][32];
    int w = threadIdx.x >> 5;
    int lane = threadIdx.x & 31;
    int t = blockIdx.x * 8 + w;
    if (t >= N_NODES) return;

    int start = d_off[t];
    int end = d_off[t + 1];
    float4 st = d_stgt4[t];

    int hsel = lane >> 3;
    const __half* hwbase = d_Hwh + (long)lane * 4;
    float4 acc = make_float4(0.f, 0.f, 0.f, 0.f);
    float s0 = 0.f, s1 = 0.f, s2 = 0.f, s3 = 0.f;

    for (int base = start; base < end; base += 32) {
        int i = base + lane;
        float ax = 0.f, ay = 0.f, az = 0.f, aw = 0.f;
        int sn = 0;
        if (i < end) {
            sn = d_sorted_src[i];
            float4 e4 = d_ssrc4[sn];
            float e0 = e4.x + st.x; e0 = fmaxf(e0, 0.2f * e0);
            float e1 = e4.y + st.y; e1 = fmaxf(e1, 0.2f * e1);
            float e2 = e4.z + st.z; e2 = fmaxf(e2, 0.2f * e2);
            float e3 = e4.w + st.w; e3 = fmaxf(e3, 0.2f * e3);
            ax = __expf(e0);
            ay = __expf(e1);
            az = __expf(e2);
            aw = __expf(e3);
            s0 += ax; s1 += ay; s2 += az; s3 += aw;
        }
        sns[w][lane] = sn;
        al[w][lane] = make_float4(ax, ay, az, aw);
        __syncwarp();
        int cnt = end - base;
        if (cnt > 32) cnt = 32;
        for (int j = 0; j < cnt; j++) {
            int sj = sns[w][j];
            float a = ((const float*)&al[w][j])[hsel];
            uint2 hv = *(const uint2*)(hwbase + (long)sj * CTOT);
            float2 f01 = __half22float2(*(const __half2*)&hv.x);
            float2 f23 = __half22float2(*(const __half2*)&hv.y);
            acc.x += a * f01.x;
            acc.y += a * f01.y;
            acc.z += a * f23.x;
            acc.w += a * f23.y;
        }
        __syncwarp();
    }

#pragma unroll
    for (int off = 16; off > 0; off >>= 1) {
        s0 += __shfl_xor_sync(0xffffffffu, s0, off);
        s1 += __shfl_xor_sync(0xffffffffu, s1, off);
        s2 += __shfl_xor_sync(0xffffffffu, s2, off);
        s3 += __shfl_xor_sync(0xffffffffu, s3, off);
    }
    float sh = (hsel == 0) ? s0 : (hsel == 1) ? s1 : (hsel == 2) ? s2 : s3;
    float inv = (sh > 0.f) ? 1.f / sh : 0.f;
    acc.x *= inv; acc.y *= inv; acc.z *= inv; acc.w *= inv;

    float4 r;
    r.x = acc.x > 0.f ? acc.x : expm1f(acc.x);
    r.y = acc.y > 0.f ? acc.y : expm1f(acc.y);
    r.z = acc.z > 0.f ? acc.z : expm1f(acc.z);
    r.w = acc.w > 0.f ? acc.w : expm1f(acc.w);
    int o = (lane & 7) * 4;
    *(float4*)(out + ((long)hsel * N_NODES + t) * DOUT + o) = r;
}

// ---------------- launcher ----------------
// Two-stream fork inside the captured graph: the edge-sort chain (stream s2)
// runs concurrently with k_gemm (capture-origin stream); k_agg joins both.
// Stream/event objects are created once on the first (uncaptured) correctness
// call; the captured work and its dependencies are identical on every call.
extern "C" void kernel_launch(void* const* d_in, const int* in_sizes, int n_in,
                              void* d_out, int out_size) {
    const float* Hin  = (const float*)d_in[0];
    const int*   ei   = (const int*)d_in[1];
    const float* W    = (const float*)d_in[2];
    const float* Asrc = (const float*)d_in[3];
    const float* Atgt = (const float*)d_in[4];
    float* out = (float*)d_out;

    static cudaStream_t s2 = 0;
    static cudaEvent_t evFork = 0, evJoin = 0;
    static int inited = 0;
    if (!inited) {
        cudaStreamCreateWithFlags(&s2, cudaStreamNonBlocking);
        cudaEventCreateWithFlags(&evFork, cudaEventDisableTiming);
        cudaEventCreateWithFlags(&evJoin, cudaEventDisableTiming);
        cudaFuncSetAttribute(k_gemm,
                             cudaFuncAttributeMaxDynamicSharedMemorySize,
                             GEMM_SMEM);
        inited = 1;
    }

    // fork: s2 branches off the capture-origin (legacy) stream
    cudaEventRecord(evFork, 0);
    cudaStreamWaitEvent(s2, evFork, 0);

    // branch A (s2): edge sort machinery
    k_init<<<(N_NODES + 255) / 256, 256, 0, s2>>>((const unsigned int*)ei);
    k_hist<<<(N_EDGES + 255) / 256, 256, 0, s2>>>(ei);
    k_scan1<<<NB_SCAN, 256, 0, s2>>>();
    k_scan3<<<NB_SCAN, 1024, 0, s2>>>();
    k_scatter<<<(N_EDGES + 255) / 256, 256, 0, s2>>>(ei);
    cudaEventRecord(evJoin, s2);

    // branch B (origin stream): feature transform + scores
    k_gemm<<<(N_NODES + NPB - 1) / NPB, 256, GEMM_SMEM>>>(Hin, W, Asrc, Atgt);

    // join, then aggregate
    cudaStreamWaitEvent(0, evJoin, 0);
    k_agg<<<(N_NODES + 7) / 8, 256>>>(out);
}